// round 7
// baseline (speedup 1.0000x reference)
#include <cuda_runtime.h>
#include <cuda_bf16.h>
#include <math.h>

#define MAXN   100000
#define MAXNP  (MAXN + 64)
#define FDIM   44
#define F2DIM  88
#define K4F    11            // FDIM/4
#define FEATD  1019
#define MAXG   1024
#define MAXE   1000000
#define SCANB  1024
#define MAXNB  ((MAXN + SCANB - 1) / SCANB)
#define MMLD   66            // smem leading dim (EVEN -> LDS.64 stays 8B-aligned)

// ---------------- scratch (allocation-free rule: __device__ globals) ----------------
__device__ __align__(256) float g_bufA[MAXNP * F2DIM];
__device__ __align__(256) float g_bufB[MAXNP * F2DIM];
__device__ __align__(256) float g_dinv[MAXN];
__device__ __align__(256) int   g_indeg[MAXN];
__device__ __align__(256) int   g_cursor[MAXN];
__device__ __align__(256) int   g_off[MAXN + 1];
__device__ __align__(256) int2  g_epack[MAXE];          // (src, __float_as_int(norm))
__device__ __align__(256) int   g_partial[MAXNB + 1];
__device__ __align__(256) int   g_bofs[MAXNB + 1];
__device__ __align__(256) float g_pool[MAXG * FDIM];

// ---------------- f32x2 packed math helpers ----------------
__device__ __forceinline__ unsigned long long ffma2(unsigned long long a,
                                                    unsigned long long b,
                                                    unsigned long long c) {
    unsigned long long d;
    asm("fma.rn.f32x2 %0, %1, %2, %3;" : "=l"(d) : "l"(a), "l"(b), "l"(c));
    return d;
}
__device__ __forceinline__ unsigned long long splat2(float x) {
    unsigned long long d;
    asm("mov.b64 %0, {%1, %2};" : "=l"(d) : "r"(__float_as_uint(x)), "r"(__float_as_uint(x)));
    return d;
}
__device__ __forceinline__ unsigned long long pack2(float lo, float hi) {
    unsigned long long d;
    asm("mov.b64 %0, {%1, %2};" : "=l"(d) : "r"(__float_as_uint(lo)), "r"(__float_as_uint(hi)));
    return d;
}

// ---------------- degree count ----------------
__global__ void k_count(const int* __restrict__ dst, int* __restrict__ indeg, int E) {
    int e = blockIdx.x * blockDim.x + threadIdx.x;
    if (e < E) atomicAdd(&indeg[dst[e]], 1);
}

// ---------------- scan phase 1 (+ dinv + cursor zero fused) ----------------
__global__ void k_scan1(const int* __restrict__ indeg, int* __restrict__ off,
                        int* __restrict__ partial, float* __restrict__ dinv,
                        int* __restrict__ cursor, int n) {
    __shared__ int wsum[32];
    int tid = threadIdx.x, lane = tid & 31, wid = tid >> 5;
    int idx = blockIdx.x * SCANB + tid;
    int v = (idx < n) ? indeg[idx] : 0;
    if (idx < n) {
        dinv[idx] = rsqrtf(1.0f + (float)v);
        cursor[idx] = 0;
    }
    int incl = v;
    #pragma unroll
    for (int d = 1; d < 32; d <<= 1) {
        int t = __shfl_up_sync(0xffffffffu, incl, d);
        if (lane >= d) incl += t;
    }
    if (lane == 31) wsum[wid] = incl;
    __syncthreads();
    if (wid == 0) {
        int w = wsum[lane];
        #pragma unroll
        for (int d = 1; d < 32; d <<= 1) {
            int t = __shfl_up_sync(0xffffffffu, w, d);
            if (lane >= d) w += t;
        }
        wsum[lane] = w;
    }
    __syncthreads();
    int warpoff = (wid == 0) ? 0 : wsum[wid - 1];
    if (idx < n) off[idx] = warpoff + incl - v;
    if (tid == 0) partial[blockIdx.x] = wsum[31];
}

// ---------------- scan phase 2 (block offsets) ----------------
__global__ void k_scan2(const int* __restrict__ partial, int* __restrict__ bofs, int nb) {
    __shared__ int wsum[32];
    int tid = threadIdx.x, lane = tid & 31, wid = tid >> 5;  // 128 threads
    int v = (tid < nb) ? partial[tid] : 0;
    int incl = v;
    #pragma unroll
    for (int d = 1; d < 32; d <<= 1) {
        int t = __shfl_up_sync(0xffffffffu, incl, d);
        if (lane >= d) incl += t;
    }
    if (lane == 31) wsum[wid] = incl;
    __syncthreads();
    if (wid == 0 && lane < 4) {
        int w = wsum[lane];
        #pragma unroll
        for (int d = 1; d < 4; d <<= 1) {
            int t = __shfl_up_sync(0x0000000fu, w, d);
            if (lane >= d) w += t;
        }
        wsum[lane] = w;
    }
    __syncthreads();
    int warpoff = (wid == 0) ? 0 : wsum[wid - 1];
    if (tid < nb) bofs[tid] = warpoff + incl - v;
}

// ---------------- CSR fill (applies bofs correction inline) ----------------
__global__ void k_fill(const int* __restrict__ src, const int* __restrict__ dst,
                       const float* __restrict__ dinv, const int* __restrict__ off,
                       const int* __restrict__ bofs,
                       int* __restrict__ cursor, int2* __restrict__ ep, int E) {
    int e = blockIdx.x * blockDim.x + threadIdx.x;
    if (e >= E) return;
    int s = src[e], d = dst[e];
    int base = off[d] + bofs[d >> 10];
    int p = base + atomicAdd(&cursor[d], 1);
    ep[p] = make_int2(s, __float_as_int(dinv[s] * dinv[d]));
}

// ---------------- tiled-smem mm: t = act(h)@W (+bias) ----------------
// Block = 352 threads (11 warps), tile = 64 rows. h staged TRANSPOSED in smem
// (k-major, ld=66 even for aligned LDS.64). Warp w owns c4 = w (+11 if KOUT4=22):
// W loads warp-uniform (L1 broadcast), h via conflict-free LDS.64, f32x2 FMA.
template <int KIN, int KOUT4, int RELU, int BIAS>
__global__ void __launch_bounds__(352) k_mm(const float* __restrict__ h,
                                            const float* __restrict__ W,
                                            const float* __restrict__ bias,
                                            float* __restrict__ t, int n) {
    __shared__ float sm[KIN * MMLD];
    const int tid = threadIdx.x;
    const int row0 = blockIdx.x * 64;

    // ---- stage h tile (relu fused), transposed ----
    const int K4 = KIN / 4;
    for (int idx = tid; idx < 64 * K4; idx += 352) {
        int r  = idx / K4;
        int k4 = idx - r * K4;
        int rg = row0 + r; if (rg > n - 1) rg = n - 1;
        float4 v = ((const float4*)(h + (size_t)rg * KIN))[k4];
        if (RELU) {
            v.x = fmaxf(v.x, 0.f); v.y = fmaxf(v.y, 0.f);
            v.z = fmaxf(v.z, 0.f); v.w = fmaxf(v.w, 0.f);
        }
        int k = k4 * 4;
        sm[(k + 0) * MMLD + r] = v.x;
        sm[(k + 1) * MMLD + r] = v.y;
        sm[(k + 2) * MMLD + r] = v.z;
        sm[(k + 3) * MMLD + r] = v.w;
    }
    __syncthreads();

    // ---- compute: warp -> c4 chunk(s); lane -> rows 2l, 2l+1 ----
    const int warp = tid >> 5;
    const int lane = tid & 31;
    const ulonglong2* Wv = (const ulonglong2*)W;

    #pragma unroll
    for (int cc = 0; cc < (KOUT4 + 10) / 11; cc++) {
        int c4 = warp + cc * 11;
        if (c4 >= KOUT4) break;

        unsigned long long a00, a01, a10, a11;
        if (BIAS) {
            float4 b4 = ((const float4*)bias)[c4];
            a00 = pack2(b4.x, b4.y); a01 = pack2(b4.z, b4.w);
            a10 = a00;               a11 = a01;
        } else {
            a00 = a01 = a10 = a11 = 0ull;
        }

        #pragma unroll 4
        for (int k = 0; k < KIN; k++) {
            float2 hv = *(const float2*)&sm[k * MMLD + 2 * lane];   // even ld -> 8B aligned
            ulonglong2 wv = Wv[k * KOUT4 + c4];                     // warp-uniform
            unsigned long long s0 = splat2(hv.x);
            unsigned long long s1 = splat2(hv.y);
            a00 = ffma2(s0, wv.x, a00); a01 = ffma2(s0, wv.y, a01);
            a10 = ffma2(s1, wv.x, a10); a11 = ffma2(s1, wv.y, a11);
        }

        int r0 = row0 + 2 * lane;
        if (r0 < n) {
            ulonglong2 o; o.x = a00; o.y = a01;
            ((ulonglong2*)t)[(size_t)r0 * KOUT4 + c4] = o;
        }
        if (r0 + 1 < n) {
            ulonglong2 o; o.x = a10; o.y = a11;
            ((ulonglong2*)t)[(size_t)(r0 + 1) * KOUT4 + c4] = o;
        }
    }
}

// ---------------- F=44 aggregation, thread = (node, float4-chunk), MLP-batched gather ----------
// out[node] = [bias +] act(t[node])*dinv^2 + sum_{s in N(node)} act(t[s]) * norm
// POOL=1: atomicMax relu'd result into pool[batch[node]] instead of writing out.
template <int RELU, int BIAS, int POOL>
__global__ void __launch_bounds__(256) k_aggr(const float* __restrict__ t,
                                              const int2* __restrict__ ep,
                                              const int* __restrict__ off,
                                              const int* __restrict__ bofs,
                                              const float* __restrict__ dinv,
                                              const float* __restrict__ bias,
                                              float* __restrict__ out,
                                              const int* __restrict__ batch,
                                              float* __restrict__ pool,
                                              int n, int E) {
    int gid = blockIdx.x * 256 + threadIdx.x;
    int node = gid / K4F;
    int c4 = gid - node * K4F;
    if (node >= n) return;

    const float4* t4 = (const float4*)t;
    float dd = dinv[node];
    float sl = dd * dd;

    float4 tv = t4[(size_t)node * K4F + c4];
    if (RELU) {
        tv.x = fmaxf(tv.x, 0.f); tv.y = fmaxf(tv.y, 0.f);
        tv.z = fmaxf(tv.z, 0.f); tv.w = fmaxf(tv.w, 0.f);
    }
    float4 acc;
    if (BIAS) {
        float4 b4 = ((const float4*)bias)[c4];
        acc.x = fmaf(tv.x, sl, b4.x); acc.y = fmaf(tv.y, sl, b4.y);
        acc.z = fmaf(tv.z, sl, b4.z); acc.w = fmaf(tv.w, sl, b4.w);
    } else {
        acc.x = tv.x * sl; acc.y = tv.y * sl;
        acc.z = tv.z * sl; acc.w = tv.w * sl;
    }

    int j   = off[node] + bofs[node >> 10];
    int end = (node == n - 1) ? E : off[node + 1] + bofs[(node + 1) >> 10];

    for (; j + 8 <= end; j += 8) {
        int2 m[8];
        #pragma unroll
        for (int q = 0; q < 8; q++) m[q] = ep[j + q];
        float4 v[8];
        #pragma unroll
        for (int q = 0; q < 8; q++)
            v[q] = t4[(size_t)m[q].x * K4F + c4];
        #pragma unroll
        for (int q = 0; q < 8; q++) {
            float w = __int_as_float(m[q].y);
            float4 x = v[q];
            if (RELU) {
                x.x = fmaxf(x.x, 0.f); x.y = fmaxf(x.y, 0.f);
                x.z = fmaxf(x.z, 0.f); x.w = fmaxf(x.w, 0.f);
            }
            acc.x = fmaf(x.x, w, acc.x); acc.y = fmaf(x.y, w, acc.y);
            acc.z = fmaf(x.z, w, acc.z); acc.w = fmaf(x.w, w, acc.w);
        }
    }
    if (j + 4 <= end) {
        int2 m[4];
        #pragma unroll
        for (int q = 0; q < 4; q++) m[q] = ep[j + q];
        float4 v[4];
        #pragma unroll
        for (int q = 0; q < 4; q++)
            v[q] = t4[(size_t)m[q].x * K4F + c4];
        #pragma unroll
        for (int q = 0; q < 4; q++) {
            float w = __int_as_float(m[q].y);
            float4 x = v[q];
            if (RELU) {
                x.x = fmaxf(x.x, 0.f); x.y = fmaxf(x.y, 0.f);
                x.z = fmaxf(x.z, 0.f); x.w = fmaxf(x.w, 0.f);
            }
            acc.x = fmaf(x.x, w, acc.x); acc.y = fmaf(x.y, w, acc.y);
            acc.z = fmaf(x.z, w, acc.z); acc.w = fmaf(x.w, w, acc.w);
        }
        j += 4;
    }
    for (; j < end; j++) {
        int2 m = ep[j];
        float w = __int_as_float(m.y);
        float4 x = t4[(size_t)m.x * K4F + c4];
        if (RELU) {
            x.x = fmaxf(x.x, 0.f); x.y = fmaxf(x.y, 0.f);
            x.z = fmaxf(x.z, 0.f); x.w = fmaxf(x.w, 0.f);
        }
        acc.x = fmaf(x.x, w, acc.x); acc.y = fmaf(x.y, w, acc.y);
        acc.z = fmaf(x.z, w, acc.z); acc.w = fmaf(x.w, w, acc.w);
    }

    if (POOL) {
        int g = batch[node];
        int* pp = (int*)&pool[(size_t)g * FDIM + c4 * 4];
        atomicMax(pp + 0, __float_as_int(fmaxf(acc.x, 0.f)));
        atomicMax(pp + 1, __float_as_int(fmaxf(acc.y, 0.f)));
        atomicMax(pp + 2, __float_as_int(fmaxf(acc.z, 0.f)));
        atomicMax(pp + 3, __float_as_int(fmaxf(acc.w, 0.f)));
    } else {
        ((float4*)out)[(size_t)node * K4F + c4] = acc;
    }
}

// ---------------- final heads: 8 graphs per block ----------------
__global__ void k_final(const float* __restrict__ pool, const float* __restrict__ feat,
                        const float* __restrict__ Wg,  const float* __restrict__ bg,
                        const float* __restrict__ Wf1, const float* __restrict__ bf1,
                        const float* __restrict__ Wf2, const float* __restrict__ bf2,
                        float* __restrict__ out, int G) {
    const int GB = 8;
    int g0 = blockIdx.x * GB;
    int j = threadIdx.x;   // 128
    float acc[GB];
    float bj = bf1[j];
    #pragma unroll
    for (int i = 0; i < GB; i++) acc[i] = bj;
    #pragma unroll 2
    for (int k = 0; k < FEATD; k++) {
        float w = Wf1[k * 128 + j];
        #pragma unroll
        for (int i = 0; i < GB; i++) {
            int g = g0 + i;
            float f = (g < G) ? feat[(size_t)g * FEATD + k] : 0.0f;
            acc[i] = fmaf(f, w, acc[i]);
        }
    }
    float wf2 = Wf2[j];
    __shared__ float red[128];
    __shared__ float sums[GB];
    #pragma unroll
    for (int i = 0; i < GB; i++) {
        red[j] = fmaxf(acc[i], 0.0f) * wf2;
        __syncthreads();
        for (int o = 64; o > 0; o >>= 1) {
            if (j < o) red[j] += red[j + o];
            __syncthreads();
        }
        if (j == 0) sums[i] = red[0];
        __syncthreads();
    }
    if (j < GB) {
        int g = g0 + j;
        if (g < G) {
            float a = bg[0];
            #pragma unroll
            for (int k = 0; k < FDIM; k++)
                a = fmaf(pool[g * FDIM + k], Wg[k], a);
            out[g] = fmaxf(a, 0.0f) + sums[j] + bf2[0];
        }
    }
}

// ----------------------------------------------------------------
extern "C" void kernel_launch(void* const* d_in, const int* in_sizes, int n_in,
                              void* d_out, int out_size) {
    const float* x       = (const float*)d_in[0];
    const int*   ei      = (const int*)  d_in[1];
    const int*   batch   = (const int*)  d_in[2];
    const float* feature = (const float*)d_in[3];
    const float* W1 = (const float*)d_in[4];  const float* b1 = (const float*)d_in[5];
    const float* W2 = (const float*)d_in[6];  const float* b2 = (const float*)d_in[7];
    const float* W3 = (const float*)d_in[8];  const float* b3 = (const float*)d_in[9];
    const float* Wg = (const float*)d_in[10]; const float* bg = (const float*)d_in[11];
    const float* Wf1= (const float*)d_in[12]; const float* bf1= (const float*)d_in[13];
    const float* Wf2= (const float*)d_in[14]; const float* bf2= (const float*)d_in[15];

    const int N = in_sizes[2];
    const int E = in_sizes[1] / 2;
    const int G = in_sizes[3] / FEATD;
    const int NB = (N + SCANB - 1) / SCANB;

    float *A, *B, *dinv, *pool;
    int *indeg, *cursor, *off, *partial, *bofs;
    int2 *ep;
    cudaGetSymbolAddress((void**)&A,      g_bufA);
    cudaGetSymbolAddress((void**)&B,      g_bufB);
    cudaGetSymbolAddress((void**)&dinv,   g_dinv);
    cudaGetSymbolAddress((void**)&indeg,  g_indeg);
    cudaGetSymbolAddress((void**)&cursor, g_cursor);
    cudaGetSymbolAddress((void**)&off,    g_off);
    cudaGetSymbolAddress((void**)&ep,     g_epack);
    cudaGetSymbolAddress((void**)&partial,g_partial);
    cudaGetSymbolAddress((void**)&bofs,   g_bofs);
    cudaGetSymbolAddress((void**)&pool,   g_pool);

    const int* src = ei;
    const int* dst = ei + E;
    float* out = (float*)d_out;

    const int T = 256;
    auto blocks = [&](int work) { return (work + T - 1) / T; };
    int mmgrid = (N + 63) / 64;

    // ---- CSR build + norms ----
    cudaMemsetAsync(indeg, 0, N * sizeof(int));
    cudaMemsetAsync(pool, 0, (size_t)G * FDIM * sizeof(float));  // relu identity
    k_count<<<blocks(E), T>>>(dst, indeg, E);
    k_scan1<<<NB, SCANB>>>(indeg, off, partial, dinv, cursor, N);
    k_scan2<<<1, 128>>>(partial, bofs, NB);

    // mm1 is CSR-independent
    k_mm<FDIM, K4F, 0, 0><<<mmgrid, 352>>>(x, W1, nullptr, A, N);
    k_fill<<<blocks(E), T>>>(src, dst, dinv, off, bofs, cursor, ep, E);

    // B = Agg(A)+b1 ; A = Agg(relu(B)) ; B = A@W2+b2 ; A = relu(B)@W3 ; pool = segmax(relu(Agg(A)+b3))
    k_aggr<0, 1, 0><<<blocks(N * K4F), T>>>(A, ep, off, bofs, dinv, b1, B, nullptr, nullptr, N, E);
    k_aggr<1, 0, 0><<<blocks(N * K4F), T>>>(B, ep, off, bofs, dinv, nullptr, A, nullptr, nullptr, N, E);
    k_mm<FDIM, F2DIM / 4, 0, 1><<<mmgrid, 352>>>(A, W2, b2, B, N);
    k_mm<F2DIM, K4F, 1, 0><<<mmgrid, 352>>>(B, W3, nullptr, A, N);
    k_aggr<0, 1, 1><<<blocks(N * K4F), T>>>(A, ep, off, bofs, dinv, b3, nullptr, batch, pool, N, E);

    // ---- heads ----
    k_final<<<(G + 7) / 8, 128>>>(pool, feature, Wg, bg, Wf1, bf1, Wf2, bf2, out, G);
}